// round 10
// baseline (speedup 1.0000x reference)
#include <cuda_runtime.h>
#include <cuda_fp16.h>
#include <math.h>

// ---------------------------------------------------------------------------
// Decoder pipeline (3 launches; prep split so the register-heavy precompute
// cannot poison the transpose kernel's allocation):
//   k_transpose  : 1024 blocks, 64 texels/blk -> g_tex16 [65536][32] fp16
//                  (64B rows) + g_texE4 quad plane (8B/texel). ~16 regs.
//   k_precompute : per-image lighting math -> g_params, b out (reg-heavy, tiny)
//   k_main       : warp-cooperative gather (8 lanes x 4 pixel-slots),
//                  half2 bilinear+dot, fused elementwise, all outputs
// Output layout (flat f32): rgb[N*3*S], shade[N*S], spec[N*3*S], blood[N*S],
//   mel[N*S], b[N*2], raw[N*3*S]   (S=4096)
// ---------------------------------------------------------------------------

#define NPIX    65536
#define IMG2    4096
#define MAXN    256
#define TROW    40          // smem transpose row pitch in halves (80B)

__device__ __half  g_tex16[(NPIX + 16) * 32];   // 4 MB, 64B per texel row (+pad)
__device__ uint2   g_texE4[NPIX + 16];          // 512 KB quad plane
__device__ float   g_params[MAXN * 128];        // ES[108] G2[9] lc[3]

__constant__ float c_S0[33] = {94.8f,104.8f,105.9f,96.8f,113.9f,125.6f,125.5f,121.3f,121.3f,113.5f,113.1f,110.8f,106.5f,108.8f,105.3f,104.4f,100.0f,96.0f,95.1f,89.1f,90.5f,90.3f,88.4f,84.0f,85.1f,81.9f,82.6f,84.9f,81.3f,71.9f,74.3f,76.4f,63.3f};
__constant__ float c_S1[33] = {43.4f,46.3f,43.9f,37.1f,36.7f,35.9f,32.6f,27.9f,24.3f,20.1f,16.2f,13.2f,8.6f,6.1f,4.2f,1.9f,0.0f,-1.6f,-3.5f,-3.5f,-5.8f,-7.2f,-8.6f,-9.5f,-10.9f,-10.7f,-12.0f,-14.0f,-13.6f,-12.0f,-13.3f,-12.9f,-10.6f};
__constant__ float c_S2[33] = {-1.1f,-0.5f,-0.7f,-1.2f,-2.6f,-2.9f,-2.8f,-2.6f,-2.6f,-1.8f,-1.5f,-1.3f,-1.2f,-1.0f,-0.5f,-0.3f,0.0f,0.2f,0.5f,2.1f,3.2f,4.1f,4.7f,5.1f,6.7f,7.3f,8.6f,9.8f,10.2f,8.3f,9.6f,8.5f,7.0f};
__constant__ float c_X[9]  = {3.2406f,-1.537f,-0.498f,-0.968f,1.8758f,0.0415f,0.0557f,-0.204f,1.057f};

// --- transpose: 1024 blocks x 64 texels, standalone (low-register) -----------
__global__ void __launch_bounds__(256) k_transpose(const float* __restrict__ sc)
{
    __shared__ __align__(16) __half tile[64 * TROW];   // 5 KB
    const int bid  = blockIdx.x;
    const int tid  = threadIdx.x;
    const int base = bid * 64;           // 64 texels per block
    const int texl = tid & 63;           // local texel 0..63
    const int part = tid >> 6;           // channel octet 0..3
    const int p    = base + texl;

    // 8 coalesced channel reads per thread (MLP=8)
    float v[8];
#pragma unroll
    for (int c = 0; c < 8; c++) v[c] = sc[(size_t)(part * 8 + c) * NPIX + p];
#pragma unroll
    for (int c = 0; c < 8; c++)
        tile[texl * TROW + part * 8 + c] = __float2half_rn(v[c]);

    // E-plane quad (octet group 0 handles it)
    if (part == 0) {
        const float* sc32 = sc + (size_t)32 * NPIX;
        const int pn  = min(p + 1,   NPIX - 1);
        const int pd  = min(p + 256, NPIX - 1);
        const int pdn = min(p + 257, NPIX - 1);
        __half2 top = __floats2half2_rn(sc32[p],  sc32[pn]);
        __half2 bot = __floats2half2_rn(sc32[pd], sc32[pdn]);
        uint2 u;
        u.x = *reinterpret_cast<unsigned*>(&top);
        u.y = *reinterpret_cast<unsigned*>(&bot);
        g_texE4[p] = u;
    }
    __syncthreads();

    // contiguous 4 KB row write: 256 uint4, one per thread
    uint4* dst = reinterpret_cast<uint4*>(g_tex16) + (size_t)base * 4;
    const int texw = tid >> 2, pw = tid & 3;
    dst[(size_t)texw * 4 + pw] =
        reinterpret_cast<const uint4*>(tile + texw * TROW)[pw];
}

// --- per-image precompute (standalone; register pressure isolated here) ------
__global__ void k_precompute(
    const float* __restrict__ lighting, const float* __restrict__ illA,
    const float* __restrict__ illF, const float* __restrict__ pcaMeans,
    const float* __restrict__ pcaComp, const float* __restrict__ tmat,
    float* __restrict__ outB, int N)
{
    int n = blockIdx.x * blockDim.x + threadIdx.x;
    if (n >= N) return;
    const float* lp = lighting + (size_t)n * 17;

    float mx = lp[0];
#pragma unroll
    for (int j = 1; j < 14; j++) mx = fmaxf(mx, lp[j]);
    float w[14], wsum = 0.f;
#pragma unroll
    for (int j = 0; j < 14; j++) { w[j] = expf(lp[j] - mx); wsum += w[j]; }
    float winv = 1.f / wsum;
    float wA = w[0] * winv, wD = w[1] * winv;
    float fw[12];
#pragma unroll
    for (int j = 0; j < 12; j++) fw[j] = w[j + 2] * winv;

    float colorTemp = 1.f / (1.f + expf(-lp[14]));
    float b0 = 6.f / (1.f + expf(-lp[15])) - 3.f;
    float b1 = 6.f / (1.f + expf(-lp[16])) - 3.f;
    outB[2 * n] = b0; outB[2 * n + 1] = b1;

    float t = colorTemp * 21000.f + 4000.f;
    float it = 1.f / t;
    float x = (t <= 7000.f)
        ? ((-4607000000.f * it + 2967800.f) * it + 99.11f) * it + 0.244063f
        : ((-2006400000.f * it + 1901800.f) * it + 247.48f) * it + 0.23704f;
    float y  = -3.f * x * x + 2.87f * x - 0.275f;
    float m  = 0.0241f + 0.2562f * x - 0.7341f * y;
    float m1 = (-1.3515f - 1.7703f * x + 5.9114f * y) / m;
    float m2 = (0.03f - 31.4424f * x + 30.0717f * y) / m;
    float s[33]; float ssum = 0.f;
#pragma unroll
    for (int k = 0; k < 33; k++) { s[k] = c_S0[k] + m1 * c_S1[k] + m2 * c_S2[k]; ssum += s[k]; }
    float sinv = 1.f / ssum;

    float e[33]; float esum = 0.f;
    for (int k = 0; k < 33; k++) {
        float ef = 0.f;
#pragma unroll
        for (int j = 0; j < 12; j++) ef += fw[j] * illF[k * 12 + j];
        float ev = wA * illA[k] + wD * s[k] * sinv + ef;
        e[k] = ev; esum += ev;
    }
    float einv = 1.f / esum;

    float lc[3] = {0.f, 0.f, 0.f};
    float* P = g_params + (size_t)n * 128;
    for (int c = 0; c < 3; c++) {
        for (int k = 0; k < 33; k++) {
            int i = c * 33 + k;
            float Sv = fmaxf(b0 * pcaComp[2 * i] + b1 * pcaComp[2 * i + 1] + pcaMeans[i], 0.f);
            lc[c] += Sv;
            P[c * 36 + k] = e[k] * einv * Sv;
        }
        P[c * 36 + 33] = 0.f; P[c * 36 + 34] = 0.f; P[c * 36 + 35] = 0.f;
    }

    float tx = (b0 * (1.f / 3.f) + 1.f) * 0.5f * 127.f;
    float ty = (b1 * (1.f / 3.f) + 1.f) * 0.5f * 127.f;
    float fx0 = floorf(tx), fy0 = floorf(ty);
    float wx = tx - fx0, wy = ty - fy0;
    int x0 = min(max((int)fx0, 0), 127), y0 = min(max((int)fy0, 0), 127);
    int x1 = min(x0 + 1, 127),           y1 = min(y0 + 1, 127);
    float w00 = (1.f - wx) * (1.f - wy), w01 = wx * (1.f - wy);
    float w10 = (1.f - wx) * wy,         w11 = wx * wy;
    float T[9];
#pragma unroll
    for (int ch = 0; ch < 9; ch++) {
        const float* tp = tmat + (size_t)ch * 128 * 128;
        T[ch] = w00 * tp[y0 * 128 + x0] + w01 * tp[y0 * 128 + x1]
              + w10 * tp[y1 * 128 + x0] + w11 * tp[y1 * 128 + x1];
    }
    for (int o = 0; o < 3; o++)
        for (int c = 0; c < 3; c++) {
            float g = c_X[o * 3 + 0] * T[c * 3 + 0]
                    + c_X[o * 3 + 1] * T[c * 3 + 1]
                    + c_X[o * 3 + 2] * T[c * 3 + 2];
            P[108 + o * 3 + c] = g / lc[c];
        }
    P[117] = lc[0]; P[118] = lc[1]; P[119] = lc[2];
}

// --- main kernel (unchanged from R9) -----------------------------------------
__global__ void __launch_bounds__(256, 4) k_main(
    const float* __restrict__ mel, const float* __restrict__ blood,
    const float* __restrict__ shade, const float* __restrict__ spec,
    float* __restrict__ out, int N)
{
    const int n    = blockIdx.y;
    const int tid  = threadIdx.x;
    const int lane = tid & 31;
    const int sub  = lane & 7;

    __shared__ float sp[120];
    if (tid < 120) sp[tid] = g_params[(size_t)n * 128 + tid];
    __syncthreads();

    const size_t NS = (size_t)N * IMG2;
    float* o_rgb   = out;
    float* o_shade = out + 3 * NS;
    float* o_spec  = out + 4 * NS;
    float* o_blood = out + 7 * NS;
    float* o_mel   = out + 8 * NS;
    float* o_raw   = out + 9 * NS + 2 * (size_t)N;

    // ----- Phase A -----
    const int p   = blockIdx.x * 256 + tid;
    const size_t idx = (size_t)n * IMG2 + p;
    const float mv = mel[idx], bv = blood[idx], sv = shade[idx];
    const float sv0 = spec[((size_t)n * 3 + 0) * IMG2 + p];
    const float sv1 = spec[((size_t)n * 3 + 1) * IMG2 + p];
    const float sv2 = spec[((size_t)n * 3 + 2) * IMG2 + p];

    const float ms = 2.f / (1.f + __expf(-mv)) - 1.f;
    const float bs = 2.f / (1.f + __expf(-bv)) - 1.f;

    const float tx = (ms + 1.f) * 127.5f;
    const float ty = (bs + 1.f) * 127.5f;
    const float fx0 = floorf(tx), fy0 = floorf(ty);
    float wx = tx - fx0, wy = ty - fy0;
    const int x0 = min(max((int)fx0, 0), 255);
    const int y0 = min(max((int)fy0, 0), 255);
    const int y1 = min(y0 + 1, 255);
    const int off00 = y0 * 256 + x0;     // < 65536
    const int off10 = y1 * 256 + x0;     // < 65536

    const float w00 = (1.f - wx) * (1.f - wy), w01 = wx * (1.f - wy);
    const float w10 = (1.f - wx) * wy,         w11 = wx * wy;

    const float shadeE = __expf(sv);
    const float se0 = __expf(sv0) * sp[117];
    const float se1 = __expf(sv1) * sp[118];
    const float se2 = __expf(sv2) * sp[119];

    // channel-32: one 8B quad load per pixel
    float er;
    {
        uint2 u = g_texE4[off00];
        __half2 th = *reinterpret_cast<__half2*>(&u.x);
        __half2 bh = *reinterpret_cast<__half2*>(&u.y);
        float2 tf = __half22float2(th);
        float2 bf = __half22float2(bh);
        er = w00 * tf.x + w01 * tf.y + w10 * bf.x + w11 * bf.y;
    }
    float d0 = sp[32]  * er;
    float d1 = sp[68]  * er;
    float d2 = sp[104] * er;

    o_mel[idx]   = ms;
    o_blood[idx] = bs;
    o_shade[idx] = shadeE;
    {
        const size_t b3 = ((size_t)n * 3) * IMG2 + p;
        o_spec[b3] = se0; o_spec[b3 + IMG2] = se1; o_spec[b3 + 2 * IMG2] = se2;
    }

    const unsigned packedOff = (unsigned)off00 | ((unsigned)off10 << 16);
    unsigned wbits;
    {
        __half2 wpack = __floats2half2_rn(wx, wy);
        wbits = *reinterpret_cast<unsigned*>(&wpack);
    }

    // ----- Phase B: cooperative gather -----
    const int k0 = (sub & 3) * 8;
    __half2 esA[4], esB[4], esC[4];
#pragma unroll
    for (int j = 0; j < 4; j++) {
        esA[j] = __floats2half2_rn(sp[      k0 + 2*j], sp[      k0 + 2*j + 1]);
        esB[j] = __floats2half2_rn(sp[36  + k0 + 2*j], sp[36  + k0 + 2*j + 1]);
        esC[j] = __floats2half2_rn(sp[72  + k0 + 2*j], sp[72  + k0 + 2*j + 1]);
    }

    const uint4* texu = reinterpret_cast<const uint4*>(g_tex16);

#pragma unroll
    for (int r = 0; r < 8; r++) {
        const int src = (lane & 24) + r;
        const unsigned po = __shfl_sync(0xffffffffu, packedOff, src);
        const unsigned pw = __shfl_sync(0xffffffffu, wbits, src);
        const int o00 = (int)(po & 0xffffu);
        const int o10 = (int)(po >> 16);
        float swx, swy;
        {
            __half2 wh = *reinterpret_cast<const __half2*>(&pw);
            float2 wf = __half22float2(wh);
            swx = wf.x; swy = wf.y;
        }
        const float wxs = (sub < 4) ? (1.f - swx) : swx;
        const __half2 ay2 = __float2half2_rn(wxs * (1.f - swy));
        const __half2 by2 = __float2half2_rn(wxs * swy);

        const uint4 vy0 = texu[(size_t)o00 * 4 + sub];
        const uint4 vy1 = texu[(size_t)o10 * 4 + sub];
        const __half2* a = reinterpret_cast<const __half2*>(&vy0);
        const __half2* b = reinterpret_cast<const __half2*>(&vy1);

        __half2 r0 = __hfma2(by2, b[0], __hmul2(ay2, a[0]));
        __half2 r1 = __hfma2(by2, b[1], __hmul2(ay2, a[1]));
        __half2 r2 = __hfma2(by2, b[2], __hmul2(ay2, a[2]));
        __half2 r3 = __hfma2(by2, b[3], __hmul2(ay2, a[3]));

        __half2 acc0 = __hmul2(esA[0], r0);
        acc0 = __hfma2(esA[1], r1, acc0);
        acc0 = __hfma2(esA[2], r2, acc0);
        acc0 = __hfma2(esA[3], r3, acc0);
        __half2 acc1 = __hmul2(esB[0], r0);
        acc1 = __hfma2(esB[1], r1, acc1);
        acc1 = __hfma2(esB[2], r2, acc1);
        acc1 = __hfma2(esB[3], r3, acc1);
        __half2 acc2 = __hmul2(esC[0], r0);
        acc2 = __hfma2(esC[1], r1, acc2);
        acc2 = __hfma2(esC[2], r2, acc2);
        acc2 = __hfma2(esC[3], r3, acc2);

        __half2 t01 = __halves2half2(
            __hadd(__low2half(acc0), __high2half(acc0)),
            __hadd(__low2half(acc1), __high2half(acc1)));
        float t2 = __low2float(acc2) + __high2float(acc2);

        unsigned u01 = *reinterpret_cast<unsigned*>(&t01);
        {
            unsigned o = __shfl_xor_sync(0xffffffffu, u01, 4);
            __half2 hv = __hadd2(*reinterpret_cast<__half2*>(&u01),
                                 *reinterpret_cast<__half2*>(&o));
            u01 = *reinterpret_cast<unsigned*>(&hv);
        }
        t2 += __shfl_xor_sync(0xffffffffu, t2, 4);
        {
            unsigned o = __shfl_xor_sync(0xffffffffu, u01, 2);
            __half2 hv = __hadd2(*reinterpret_cast<__half2*>(&u01),
                                 *reinterpret_cast<__half2*>(&o));
            u01 = *reinterpret_cast<unsigned*>(&hv);
        }
        t2 += __shfl_xor_sync(0xffffffffu, t2, 2);
        {
            unsigned o = __shfl_xor_sync(0xffffffffu, u01, 1);
            __half2 hv = __hadd2(*reinterpret_cast<__half2*>(&u01),
                                 *reinterpret_cast<__half2*>(&o));
            u01 = *reinterpret_cast<unsigned*>(&hv);
        }
        t2 += __shfl_xor_sync(0xffffffffu, t2, 1);

        if (sub == r) {
            __half2 hv = *reinterpret_cast<__half2*>(&u01);
            d0 += __low2float(hv);
            d1 += __high2float(hv);
            d2 += t2;
        }
    }

    // ----- Phase C -----
    const float raw0 = shadeE * d0 + se0;
    const float raw1 = shadeE * d1 + se1;
    const float raw2 = shadeE * d2 + se2;
    const float rr = fmaxf(sp[108] * raw0 + sp[109] * raw1 + sp[110] * raw2, 0.f);
    const float rg = fmaxf(sp[111] * raw0 + sp[112] * raw1 + sp[113] * raw2, 0.f);
    const float rb = fmaxf(sp[114] * raw0 + sp[115] * raw1 + sp[116] * raw2, 0.f);

    const size_t b3 = ((size_t)n * 3) * IMG2 + p;
    o_rgb[b3] = rr; o_rgb[b3 + IMG2] = rg; o_rgb[b3 + 2 * IMG2] = rb;
    o_raw[b3] = raw0; o_raw[b3 + IMG2] = raw1; o_raw[b3 + 2 * IMG2] = raw2;
}

// ---------------------------------------------------------------------------
extern "C" void kernel_launch(void* const* d_in, const int* in_sizes, int n_in,
                              void* d_out, int out_size) {
    const float* lighting  = (const float*)d_in[0];
    const float* mel       = (const float*)d_in[1];
    const float* blood     = (const float*)d_in[2];
    const float* shade     = (const float*)d_in[3];
    const float* spec      = (const float*)d_in[4];
    const float* illA      = (const float*)d_in[5];
    const float* illF      = (const float*)d_in[6];
    const float* pcaMeans  = (const float*)d_in[7];
    const float* pcaComp   = (const float*)d_in[8];
    const float* skinColor = (const float*)d_in[9];
    const float* tmatrix   = (const float*)d_in[10];
    float* out = (float*)d_out;

    int N = in_sizes[0] / 17;            // lighting [N,17]
    size_t NS = (size_t)N * IMG2;
    float* outB = out + 9 * NS;

    k_transpose<<<1024, 256>>>(skinColor);
    k_precompute<<<(N + 127) / 128, 128>>>(lighting, illA, illF, pcaMeans,
                                           pcaComp, tmatrix, outB, N);
    k_main<<<dim3(16, N), 256>>>(mel, blood, shade, spec, out, N);
}

// round 11
// speedup vs baseline: 1.0532x; 1.0532x over previous
#include <cuda_runtime.h>
#include <cuda_fp16.h>
#include <math.h>

// ---------------------------------------------------------------------------
// Decoder pipeline (2 launches):
//   k_prep : bid 0       -> per-image lighting precompute -> g_params, b out
//            bids 1..512 -> transpose skinColor[33,256,256] -> g_tex16
//                           [65536][32] fp16 (64B rows, 128 texels/blk via
//                           float2) + g_texE4 quad plane (8B/texel)
//   k_main : 2 pixels/thread, float2 I/O, warp-cooperative gather
//            (8 lanes x 4 pixel-slots, 16 rounds), half2 bilinear+dot
// Output layout (flat f32): rgb[N*3*S], shade[N*S], spec[N*3*S], blood[N*S],
//   mel[N*S], b[N*2], raw[N*3*S]   (S=4096)
// ---------------------------------------------------------------------------

#define NPIX    65536
#define IMG2    4096
#define MAXN    256
#define TROW    40          // smem transpose row pitch in halves (80B)

__device__ __half  g_tex16[(NPIX + 16) * 32];   // 4 MB, 64B per texel row (+pad)
__device__ uint2   g_texE4[NPIX + 16];          // 512 KB quad plane
__device__ float   g_params[MAXN * 128];        // ES[108] G2[9] lc[3]

__constant__ float c_S0[33] = {94.8f,104.8f,105.9f,96.8f,113.9f,125.6f,125.5f,121.3f,121.3f,113.5f,113.1f,110.8f,106.5f,108.8f,105.3f,104.4f,100.0f,96.0f,95.1f,89.1f,90.5f,90.3f,88.4f,84.0f,85.1f,81.9f,82.6f,84.9f,81.3f,71.9f,74.3f,76.4f,63.3f};
__constant__ float c_S1[33] = {43.4f,46.3f,43.9f,37.1f,36.7f,35.9f,32.6f,27.9f,24.3f,20.1f,16.2f,13.2f,8.6f,6.1f,4.2f,1.9f,0.0f,-1.6f,-3.5f,-3.5f,-5.8f,-7.2f,-8.6f,-9.5f,-10.9f,-10.7f,-12.0f,-14.0f,-13.6f,-12.0f,-13.3f,-12.9f,-10.6f};
__constant__ float c_S2[33] = {-1.1f,-0.5f,-0.7f,-1.2f,-2.6f,-2.9f,-2.8f,-2.6f,-2.6f,-1.8f,-1.5f,-1.3f,-1.2f,-1.0f,-0.5f,-0.3f,0.0f,0.2f,0.5f,2.1f,3.2f,4.1f,4.7f,5.1f,6.7f,7.3f,8.6f,9.8f,10.2f,8.3f,9.6f,8.5f,7.0f};
__constant__ float c_X[9]  = {3.2406f,-1.537f,-0.498f,-0.968f,1.8758f,0.0415f,0.0557f,-0.204f,1.057f};

__device__ __forceinline__ void precompute_image(
    int n, const float* lp, const float* illA, const float* illF,
    const float* pcaMeans, const float* pcaComp, const float* tmat,
    float* outB)
{
    float mx = lp[0];
#pragma unroll
    for (int j = 1; j < 14; j++) mx = fmaxf(mx, lp[j]);
    float w[14], wsum = 0.f;
#pragma unroll
    for (int j = 0; j < 14; j++) { w[j] = expf(lp[j] - mx); wsum += w[j]; }
    float winv = 1.f / wsum;
    float wA = w[0] * winv, wD = w[1] * winv;
    float fw[12];
#pragma unroll
    for (int j = 0; j < 12; j++) fw[j] = w[j + 2] * winv;

    float colorTemp = 1.f / (1.f + expf(-lp[14]));
    float b0 = 6.f / (1.f + expf(-lp[15])) - 3.f;
    float b1 = 6.f / (1.f + expf(-lp[16])) - 3.f;
    outB[2 * n] = b0; outB[2 * n + 1] = b1;

    float t = colorTemp * 21000.f + 4000.f;
    float it = 1.f / t;
    float x = (t <= 7000.f)
        ? ((-4607000000.f * it + 2967800.f) * it + 99.11f) * it + 0.244063f
        : ((-2006400000.f * it + 1901800.f) * it + 247.48f) * it + 0.23704f;
    float y  = -3.f * x * x + 2.87f * x - 0.275f;
    float m  = 0.0241f + 0.2562f * x - 0.7341f * y;
    float m1 = (-1.3515f - 1.7703f * x + 5.9114f * y) / m;
    float m2 = (0.03f - 31.4424f * x + 30.0717f * y) / m;
    float s[33]; float ssum = 0.f;
#pragma unroll
    for (int k = 0; k < 33; k++) { s[k] = c_S0[k] + m1 * c_S1[k] + m2 * c_S2[k]; ssum += s[k]; }
    float sinv = 1.f / ssum;

    float e[33]; float esum = 0.f;
    for (int k = 0; k < 33; k++) {
        float ef = 0.f;
#pragma unroll
        for (int j = 0; j < 12; j++) ef += fw[j] * illF[k * 12 + j];
        float ev = wA * illA[k] + wD * s[k] * sinv + ef;
        e[k] = ev; esum += ev;
    }
    float einv = 1.f / esum;

    float lc[3] = {0.f, 0.f, 0.f};
    float* P = g_params + (size_t)n * 128;
    for (int c = 0; c < 3; c++) {
        for (int k = 0; k < 33; k++) {
            int i = c * 33 + k;
            float Sv = fmaxf(b0 * pcaComp[2 * i] + b1 * pcaComp[2 * i + 1] + pcaMeans[i], 0.f);
            lc[c] += Sv;
            P[c * 36 + k] = e[k] * einv * Sv;
        }
        P[c * 36 + 33] = 0.f; P[c * 36 + 34] = 0.f; P[c * 36 + 35] = 0.f;
    }

    float tx = (b0 * (1.f / 3.f) + 1.f) * 0.5f * 127.f;
    float ty = (b1 * (1.f / 3.f) + 1.f) * 0.5f * 127.f;
    float fx0 = floorf(tx), fy0 = floorf(ty);
    float wx = tx - fx0, wy = ty - fy0;
    int x0 = min(max((int)fx0, 0), 127), y0 = min(max((int)fy0, 0), 127);
    int x1 = min(x0 + 1, 127),           y1 = min(y0 + 1, 127);
    float w00 = (1.f - wx) * (1.f - wy), w01 = wx * (1.f - wy);
    float w10 = (1.f - wx) * wy,         w11 = wx * wy;
    float T[9];
#pragma unroll
    for (int ch = 0; ch < 9; ch++) {
        const float* tp = tmat + (size_t)ch * 128 * 128;
        T[ch] = w00 * tp[y0 * 128 + x0] + w01 * tp[y0 * 128 + x1]
              + w10 * tp[y1 * 128 + x0] + w11 * tp[y1 * 128 + x1];
    }
    for (int o = 0; o < 3; o++)
        for (int c = 0; c < 3; c++) {
            float g = c_X[o * 3 + 0] * T[c * 3 + 0]
                    + c_X[o * 3 + 1] * T[c * 3 + 1]
                    + c_X[o * 3 + 2] * T[c * 3 + 2];
            P[108 + o * 3 + c] = g / lc[c];
        }
    P[117] = lc[0]; P[118] = lc[1]; P[119] = lc[2];
}

// --- prep: precompute (bid 0) + transpose (bids 1..512, 128 texels each) -----
__global__ void __launch_bounds__(256) k_prep(
    const float* __restrict__ sc,
    const float* __restrict__ lighting, const float* __restrict__ illA,
    const float* __restrict__ illF, const float* __restrict__ pcaMeans,
    const float* __restrict__ pcaComp, const float* __restrict__ tmat,
    float* __restrict__ outB, int N)
{
    const int bid = blockIdx.x;
    const int tid = threadIdx.x;

    if (bid == 0) {
        if (tid < N)
            precompute_image(tid, lighting + (size_t)tid * 17, illA, illF,
                             pcaMeans, pcaComp, tmat, outB);
        return;
    }

    __shared__ __align__(16) __half tile[128 * TROW];   // 10 KB
    const int base  = (bid - 1) * 128;   // 128 texels per block
    const int pairI = tid & 63;          // texel-pair 0..63
    const int part  = tid >> 6;          // channel octet 0..3

    // 8 channels x 2 texels per thread (float2 loads, MLP=8)
    float2 v[8];
#pragma unroll
    for (int c = 0; c < 8; c++)
        v[c] = reinterpret_cast<const float2*>(
                   sc + (size_t)(part * 8 + c) * NPIX)[(base >> 1) + pairI];
#pragma unroll
    for (int c = 0; c < 8; c++) {
        tile[(2 * pairI)     * TROW + part * 8 + c] = __float2half_rn(v[c].x);
        tile[(2 * pairI + 1) * TROW + part * 8 + c] = __float2half_rn(v[c].y);
    }

    // E-plane quad: 128 threads (part<2), one texel each
    if (part < 2) {
        const int p = base + 2 * pairI + part;
        const float* sc32 = sc + (size_t)32 * NPIX;
        const int pn  = min(p + 1,   NPIX - 1);
        const int pd  = min(p + 256, NPIX - 1);
        const int pdn = min(p + 257, NPIX - 1);
        __half2 top = __floats2half2_rn(sc32[p],  sc32[pn]);
        __half2 bot = __floats2half2_rn(sc32[pd], sc32[pdn]);
        uint2 u;
        u.x = *reinterpret_cast<unsigned*>(&top);
        u.y = *reinterpret_cast<unsigned*>(&bot);
        g_texE4[p] = u;
    }
    __syncthreads();

    // contiguous 8 KB row write: 512 uint4, two per thread
    uint4* dst = reinterpret_cast<uint4*>(g_tex16) + (size_t)base * 4;
#pragma unroll
    for (int j = 0; j < 2; j++) {
        const int i = tid + 256 * j;             // 0..511
        const int texw = i >> 2, pw = i & 3;
        dst[(size_t)texw * 4 + pw] =
            reinterpret_cast<const uint4*>(tile + texw * TROW)[pw];
    }
}

// --- main kernel: 2 pixels/thread --------------------------------------------
// Block covers 512 pixels; thread owns pixels chunk+2*tid, +1 (float2 I/O).
// Phase B: 16 rounds; round r gathers pixel-set jj=r>>3 of slot lanes.
__global__ void __launch_bounds__(256, 3) k_main(
    const float* __restrict__ mel, const float* __restrict__ blood,
    const float* __restrict__ shade, const float* __restrict__ spec,
    float* __restrict__ out, int N)
{
    const int n    = blockIdx.y;
    const int tid  = threadIdx.x;
    const int lane = tid & 31;
    const int sub  = lane & 7;
    const int chunk = blockIdx.x * 512;

    __shared__ float sp[120];
    if (tid < 120) sp[tid] = g_params[(size_t)n * 128 + tid];
    __syncthreads();

    const size_t NS = (size_t)N * IMG2;
    float* o_rgb   = out;
    float* o_shade = out + 3 * NS;
    float* o_spec  = out + 4 * NS;
    float* o_blood = out + 7 * NS;
    float* o_mel   = out + 8 * NS;
    float* o_raw   = out + 9 * NS + 2 * (size_t)N;

    const size_t baseP = (size_t)n * IMG2 + chunk;      // pixel base (float2-aligned)
    const float2 mv2 = reinterpret_cast<const float2*>(mel   + baseP)[tid];
    const float2 bv2 = reinterpret_cast<const float2*>(blood + baseP)[tid];
    const float2 sv2 = reinterpret_cast<const float2*>(shade + baseP)[tid];
    float2 sp2[3];
#pragma unroll
    for (int c = 0; c < 3; c++)
        sp2[c] = reinterpret_cast<const float2*>(
                     spec + ((size_t)n * 3 + c) * IMG2 + chunk)[tid];

    // per-pixel state
    float msA[2], bsA[2], shE[2];
    float se0A[2], se1A[2], se2A[2];
    float d0A[2], d1A[2], d2A[2];
    unsigned pOff[2], wB[2];

#pragma unroll
    for (int jj = 0; jj < 2; jj++) {
        const float mv  = jj ? mv2.y : mv2.x;
        const float bv  = jj ? bv2.y : bv2.x;
        const float sv  = jj ? sv2.y : sv2.x;
        const float sv0 = jj ? sp2[0].y : sp2[0].x;
        const float sv1 = jj ? sp2[1].y : sp2[1].x;
        const float sv2v = jj ? sp2[2].y : sp2[2].x;

        const float ms = 2.f / (1.f + __expf(-mv)) - 1.f;
        const float bs = 2.f / (1.f + __expf(-bv)) - 1.f;
        msA[jj] = ms; bsA[jj] = bs;

        const float tx = (ms + 1.f) * 127.5f;
        const float ty = (bs + 1.f) * 127.5f;
        const float fx0 = floorf(tx), fy0 = floorf(ty);
        const float wx = tx - fx0, wy = ty - fy0;
        const int x0 = min(max((int)fx0, 0), 255);
        const int y0 = min(max((int)fy0, 0), 255);
        const int y1 = min(y0 + 1, 255);
        const int off00 = y0 * 256 + x0;
        const int off10 = y1 * 256 + x0;

        const float w00 = (1.f - wx) * (1.f - wy), w01 = wx * (1.f - wy);
        const float w10 = (1.f - wx) * wy,         w11 = wx * wy;

        shE[jj]  = __expf(sv);
        se0A[jj] = __expf(sv0)  * sp[117];
        se1A[jj] = __expf(sv1)  * sp[118];
        se2A[jj] = __expf(sv2v) * sp[119];

        // channel-32 quad
        uint2 u = g_texE4[off00];
        __half2 th = *reinterpret_cast<__half2*>(&u.x);
        __half2 bh = *reinterpret_cast<__half2*>(&u.y);
        float2 tf = __half22float2(th);
        float2 bf = __half22float2(bh);
        const float er = w00 * tf.x + w01 * tf.y + w10 * bf.x + w11 * bf.y;
        d0A[jj] = sp[32]  * er;
        d1A[jj] = sp[68]  * er;
        d2A[jj] = sp[104] * er;

        pOff[jj] = (unsigned)off00 | ((unsigned)off10 << 16);
        __half2 wpack = __floats2half2_rn(wx, wy);
        wB[jj] = *reinterpret_cast<unsigned*>(&wpack);
    }

    // cheap outputs (float2, coalesced)
    reinterpret_cast<float2*>(o_mel   + baseP)[tid] = make_float2(msA[0], msA[1]);
    reinterpret_cast<float2*>(o_blood + baseP)[tid] = make_float2(bsA[0], bsA[1]);
    reinterpret_cast<float2*>(o_shade + baseP)[tid] = make_float2(shE[0], shE[1]);
    {
        const size_t b3 = ((size_t)n * 3) * IMG2 + chunk;
        reinterpret_cast<float2*>(o_spec + b3)[tid]            = make_float2(se0A[0], se0A[1]);
        reinterpret_cast<float2*>(o_spec + b3 + IMG2)[tid]     = make_float2(se1A[0], se1A[1]);
        reinterpret_cast<float2*>(o_spec + b3 + 2 * IMG2)[tid] = make_float2(se2A[0], se2A[1]);
    }

    // ----- Phase B: cooperative gather, 16 rounds -----
    const int k0 = (sub & 3) * 8;
    __half2 esA[4], esB[4], esC[4];
#pragma unroll
    for (int j = 0; j < 4; j++) {
        esA[j] = __floats2half2_rn(sp[      k0 + 2*j], sp[      k0 + 2*j + 1]);
        esB[j] = __floats2half2_rn(sp[36  + k0 + 2*j], sp[36  + k0 + 2*j + 1]);
        esC[j] = __floats2half2_rn(sp[72  + k0 + 2*j], sp[72  + k0 + 2*j + 1]);
    }

    const uint4* texu = reinterpret_cast<const uint4*>(g_tex16);

#pragma unroll
    for (int r = 0; r < 16; r++) {
        const int jj = r >> 3;
        const int rr = r & 7;
        const int src = (lane & 24) + rr;
        const unsigned po = __shfl_sync(0xffffffffu, pOff[jj], src);
        const unsigned pw = __shfl_sync(0xffffffffu, wB[jj], src);
        const int o00 = (int)(po & 0xffffu);
        const int o10 = (int)(po >> 16);
        float swx, swy;
        {
            __half2 wh = *reinterpret_cast<const __half2*>(&pw);
            float2 wf = __half22float2(wh);
            swx = wf.x; swy = wf.y;
        }
        const float wxs = (sub < 4) ? (1.f - swx) : swx;
        const __half2 ay2 = __float2half2_rn(wxs * (1.f - swy));
        const __half2 by2 = __float2half2_rn(wxs * swy);

        const uint4 vy0 = texu[(size_t)o00 * 4 + sub];
        const uint4 vy1 = texu[(size_t)o10 * 4 + sub];
        const __half2* a = reinterpret_cast<const __half2*>(&vy0);
        const __half2* b = reinterpret_cast<const __half2*>(&vy1);

        __half2 r0 = __hfma2(by2, b[0], __hmul2(ay2, a[0]));
        __half2 r1 = __hfma2(by2, b[1], __hmul2(ay2, a[1]));
        __half2 r2 = __hfma2(by2, b[2], __hmul2(ay2, a[2]));
        __half2 r3 = __hfma2(by2, b[3], __hmul2(ay2, a[3]));

        __half2 acc0 = __hmul2(esA[0], r0);
        acc0 = __hfma2(esA[1], r1, acc0);
        acc0 = __hfma2(esA[2], r2, acc0);
        acc0 = __hfma2(esA[3], r3, acc0);
        __half2 acc1 = __hmul2(esB[0], r0);
        acc1 = __hfma2(esB[1], r1, acc1);
        acc1 = __hfma2(esB[2], r2, acc1);
        acc1 = __hfma2(esB[3], r3, acc1);
        __half2 acc2 = __hmul2(esC[0], r0);
        acc2 = __hfma2(esC[1], r1, acc2);
        acc2 = __hfma2(esC[2], r2, acc2);
        acc2 = __hfma2(esC[3], r3, acc2);

        __half2 t01 = __halves2half2(
            __hadd(__low2half(acc0), __high2half(acc0)),
            __hadd(__low2half(acc1), __high2half(acc1)));
        float t2 = __low2float(acc2) + __high2float(acc2);

        unsigned u01 = *reinterpret_cast<unsigned*>(&t01);
        {
            unsigned o = __shfl_xor_sync(0xffffffffu, u01, 4);
            __half2 hv = __hadd2(*reinterpret_cast<__half2*>(&u01),
                                 *reinterpret_cast<__half2*>(&o));
            u01 = *reinterpret_cast<unsigned*>(&hv);
        }
        t2 += __shfl_xor_sync(0xffffffffu, t2, 4);
        {
            unsigned o = __shfl_xor_sync(0xffffffffu, u01, 2);
            __half2 hv = __hadd2(*reinterpret_cast<__half2*>(&u01),
                                 *reinterpret_cast<__half2*>(&o));
            u01 = *reinterpret_cast<unsigned*>(&hv);
        }
        t2 += __shfl_xor_sync(0xffffffffu, t2, 2);
        {
            unsigned o = __shfl_xor_sync(0xffffffffu, u01, 1);
            __half2 hv = __hadd2(*reinterpret_cast<__half2*>(&u01),
                                 *reinterpret_cast<__half2*>(&o));
            u01 = *reinterpret_cast<unsigned*>(&hv);
        }
        t2 += __shfl_xor_sync(0xffffffffu, t2, 1);

        if (sub == rr) {
            __half2 hv = *reinterpret_cast<__half2*>(&u01);
            d0A[jj] += __low2float(hv);
            d1A[jj] += __high2float(hv);
            d2A[jj] += t2;
        }
    }

    // ----- Phase C (both pixels) -----
    float rrA[2], rgA[2], rbA[2], raw0A[2], raw1A[2], raw2A[2];
#pragma unroll
    for (int jj = 0; jj < 2; jj++) {
        const float raw0 = shE[jj] * d0A[jj] + se0A[jj];
        const float raw1 = shE[jj] * d1A[jj] + se1A[jj];
        const float raw2 = shE[jj] * d2A[jj] + se2A[jj];
        raw0A[jj] = raw0; raw1A[jj] = raw1; raw2A[jj] = raw2;
        rrA[jj] = fmaxf(sp[108] * raw0 + sp[109] * raw1 + sp[110] * raw2, 0.f);
        rgA[jj] = fmaxf(sp[111] * raw0 + sp[112] * raw1 + sp[113] * raw2, 0.f);
        rbA[jj] = fmaxf(sp[114] * raw0 + sp[115] * raw1 + sp[116] * raw2, 0.f);
    }

    const size_t b3 = ((size_t)n * 3) * IMG2 + chunk;
    reinterpret_cast<float2*>(o_rgb + b3)[tid]            = make_float2(rrA[0], rrA[1]);
    reinterpret_cast<float2*>(o_rgb + b3 + IMG2)[tid]     = make_float2(rgA[0], rgA[1]);
    reinterpret_cast<float2*>(o_rgb + b3 + 2 * IMG2)[tid] = make_float2(rbA[0], rbA[1]);
    reinterpret_cast<float2*>(o_raw + b3)[tid]            = make_float2(raw0A[0], raw0A[1]);
    reinterpret_cast<float2*>(o_raw + b3 + IMG2)[tid]     = make_float2(raw1A[0], raw1A[1]);
    reinterpret_cast<float2*>(o_raw + b3 + 2 * IMG2)[tid] = make_float2(raw2A[0], raw2A[1]);
}

// ---------------------------------------------------------------------------
extern "C" void kernel_launch(void* const* d_in, const int* in_sizes, int n_in,
                              void* d_out, int out_size) {
    const float* lighting  = (const float*)d_in[0];
    const float* mel       = (const float*)d_in[1];
    const float* blood     = (const float*)d_in[2];
    const float* shade     = (const float*)d_in[3];
    const float* spec      = (const float*)d_in[4];
    const float* illA      = (const float*)d_in[5];
    const float* illF      = (const float*)d_in[6];
    const float* pcaMeans  = (const float*)d_in[7];
    const float* pcaComp   = (const float*)d_in[8];
    const float* skinColor = (const float*)d_in[9];
    const float* tmatrix   = (const float*)d_in[10];
    float* out = (float*)d_out;

    int N = in_sizes[0] / 17;            // lighting [N,17]
    size_t NS = (size_t)N * IMG2;
    float* outB = out + 9 * NS;

    k_prep<<<513, 256>>>(skinColor, lighting, illA, illF, pcaMeans,
                         pcaComp, tmatrix, outB, N);
    k_main<<<dim3(8, N), 256>>>(mel, blood, shade, spec, out, N);
}